// round 7
// baseline (speedup 1.0000x reference)
#include <cuda_runtime.h>
#include <cstdint>

// ---------------- problem constants ----------------
#define BATCH   32
#define NTOK    1024
#define DDIM    1024
#define MFF     4096
#define LN_EPS  1e-5f

#define MS_SPLIT 16
#define F1_SPLIT 16
#define F2_SPLIT 64

#define PF_BLOCKS 48              // prefetch blocks prepended to gauss/stats

// ---------------- scratch ----------------
__device__ float g_x    [BATCH * NTOK];
__device__ float g_qstat[64];                 // (mean, rstd) per Q row
__device__ float g_xraw [64];                 // (sum, sumsq) per x row (atomics)
__device__ float g_part [4194304];            // split-K partials (16 MB)
__device__ float g_sink;                      // DCE-blocker for prefetch

#define MU_OFF  0                             // 16*32*1024 = 524288
#define SIG_OFF 524288
#define W1_OFF  0                             // 16*32*4096 = 2097152 (reuses mu/sig)
#define W2_OFF  2097152                       // 64*32*1024 = 2097152

// dynamic smem: A panel [64][68] + W panel [64][264]
#define GEMM_SMEM ((64 * 68 + 64 * 264) * 4)  // 84992 B

// =====================================================================
// helper: stream a weight range through L2 (normal caching), no output
// =====================================================================
__device__ __forceinline__ void prefetch_l2(const float* base, int nFloat4,
                                            int slot, int nSlots)
{
    const float4* p = reinterpret_cast<const float4*>(base);
    float acc = 0.f;
    for (int idx = slot * 256 + threadIdx.x; idx < nFloat4; idx += nSlots * 256) {
        const float4 v = __ldg(&p[idx]);
        acc += v.x + v.y + v.z + v.w;
    }
    if (acc == 1.2345678e38f) g_sink = acc;   // never true; blocks DCE
}

// =====================================================================
// block 0: Q row stats + zero x-stat accumulators.
// blocks 1..PF_BLOCKS*2: prefetch mu_w / sigma_w into L2.
// =====================================================================
__global__ void stats_kernel(const float* __restrict__ Q,
                             const float* __restrict__ mu_w,
                             const float* __restrict__ sigma_w)
{
    if (blockIdx.x > 0) {
        const int pb = blockIdx.x - 1;                       // 0..2*PF-1
        if (pb < PF_BLOCKS)
            prefetch_l2(mu_w,    NTOK * NTOK / 4, pb, PF_BLOCKS);
        else
            prefetch_l2(sigma_w, NTOK * NTOK / 4, pb - PF_BLOCKS, PF_BLOCKS);
        return;
    }
    const int tid = threadIdx.x;
    if (tid < 64) g_xraw[tid] = 0.f;
    const int r = tid >> 5, lane = tid & 31;
    const float4* p = reinterpret_cast<const float4*>(Q + r * NTOK);
    float s = 0.f, ss = 0.f;
    #pragma unroll
    for (int i = 0; i < 8; ++i) {
        float4 v = p[lane + 32 * i];
        s  += v.x + v.y + v.z + v.w;
        ss += v.x*v.x + v.y*v.y + v.z*v.z + v.w*v.w;
    }
    #pragma unroll
    for (int o = 16; o; o >>= 1) {
        s  += __shfl_xor_sync(0xffffffffu, s,  o);
        ss += __shfl_xor_sync(0xffffffffu, ss, o);
    }
    if (lane == 0) {
        const float mean = s * (1.0f / NTOK);
        const float var  = ss * (1.0f / NTOK) - mean * mean;
        g_qstat[2 * r]     = mean;
        g_qstat[2 * r + 1] = rsqrtf(var + LN_EPS);
    }
}

// =====================================================================
// Split-K GEMM. Block tile 32(M) x 256(N); K strip 64 per block.
// Each thread prefetches its whole W row strip with 16 back-to-back
// LDG.128 (weights are L2-resident), dumps to a whole-strip smem panel,
// then computes 64 kk with NO syncs: 1 LDS.128 (W) + 4 broadcast
// LDS.128 (dup A) + 16 fma.f32x2 per kk.
// AMODE 0: A = LN(Q) (g_qstat)  1: A = LN(g_x) (g_xraw)
// AMODE 2: A = silu(sum of F1_SPLIT partials + b1)
// gridDim = (N/256, nsplit, nz); z selects W0/W1 (mu/sigma fusion).
// =====================================================================
template<int AMODE>
__global__ __launch_bounds__(256, 2)
void gemm_kernel(const float* __restrict__ W0, const float* __restrict__ W1,
                 int ldw, int N, int partOff, int partStrideZ,
                 const float* __restrict__ Ain,
                 const float* __restrict__ lng, const float* __restrict__ lnb,
                 const float* __restrict__ b1)
{
    extern __shared__ __align__(16) float smem[];
    float* a_s = smem;                  // [64][68] dup A
    float* w_s = smem + 64 * 68;        // [64][264] plain W

    const int tid = threadIdx.x;
    const float* __restrict__ W = (blockIdx.z == 0) ? W0 : W1;
    float* __restrict__ P = g_part + partOff + (size_t)blockIdx.z * partStrideZ;

    const int j0    = blockIdx.x * 256;
    const int split = blockIdx.y;
    const int kOff  = split * 64;

    const float* Wrow = W + (size_t)(j0 + tid) * ldw + kOff;

    // ---- prefetch W strip: 16 back-to-back LDG.128 (L2-resident) ----
    float4 wreg[16];
    #pragma unroll
    for (int j = 0; j < 16; ++j)
        wreg[j] = *reinterpret_cast<const float4*>(Wrow + 4 * j);

    // ---- build A panel ----
    const int ra = tid >> 3, ca = tid & 7;
    float mean = 0.f, rs = 0.f;
    if (AMODE == 0) { mean = g_qstat[2 * ra]; rs = g_qstat[2 * ra + 1]; }
    if (AMODE == 1) {
        const float s  = g_xraw[2 * ra];
        const float ss = g_xraw[2 * ra + 1];
        mean = s * (1.0f / NTOK);
        rs   = rsqrtf(ss * (1.0f / NTOK) - mean * mean + LN_EPS);
    }
    const float* Arow = (AMODE == 1) ? (g_x + ra * NTOK)
                      : (AMODE == 0) ? (Ain + ra * NTOK) : nullptr;

    #pragma unroll
    for (int h = 0; h < 2; ++h) {
        const int klocal = ca * 8 + h * 4;
        const int kc     = kOff + klocal;
        float av[4];
        if (AMODE < 2) {
            const float4 fa = *reinterpret_cast<const float4*>(Arow + kc);
            const float4 fg = *reinterpret_cast<const float4*>(lng + kc);
            const float4 fb = *reinterpret_cast<const float4*>(lnb + kc);
            av[0] = (fa.x - mean) * rs * fg.x + fb.x;
            av[1] = (fa.y - mean) * rs * fg.y + fb.y;
            av[2] = (fa.z - mean) * rs * fg.z + fb.z;
            av[3] = (fa.w - mean) * rs * fg.w + fb.w;
        } else {
            float4 v = *reinterpret_cast<const float4*>(b1 + kc);
            #pragma unroll
            for (int s = 0; s < F1_SPLIT; ++s) {
                const float4 p = *reinterpret_cast<const float4*>(
                    g_part + W1_OFF + (size_t)(s * BATCH + ra) * MFF + kc);
                v.x += p.x; v.y += p.y; v.z += p.z; v.w += p.w;
            }
            av[0] = v.x / (1.0f + __expf(-v.x));
            av[1] = v.y / (1.0f + __expf(-v.y));
            av[2] = v.z / (1.0f + __expf(-v.z));
            av[3] = v.w / (1.0f + __expf(-v.w));
        }
        #pragma unroll
        for (int j = 0; j < 4; ++j)
            *reinterpret_cast<float2*>(&a_s[(klocal + j) * 68 + 2 * ra]) =
                make_float2(av[j], av[j]);
    }

    // ---- dump W strip to smem ----
    #pragma unroll
    for (int j = 0; j < 16; ++j) {
        w_s[(4 * j + 0) * 264 + tid] = wreg[j].x;
        w_s[(4 * j + 1) * 264 + tid] = wreg[j].y;
        w_s[(4 * j + 2) * 264 + tid] = wreg[j].z;
        w_s[(4 * j + 3) * 264 + tid] = wreg[j].w;
    }
    __syncthreads();

    // ---- main loop: 64 kk, no syncs ----
    const int tx = tid & 63, ty = tid >> 6;
    const float* wp = w_s + 4 * tx;
    const float* ap = a_s + 16 * ty;

    unsigned long long acc[8][2];
    #pragma unroll
    for (int r = 0; r < 8; ++r) { acc[r][0] = 0ull; acc[r][1] = 0ull; }

    #pragma unroll 16
    for (int kk = 0; kk < 64; ++kk) {
        const ulonglong2 w = *reinterpret_cast<const ulonglong2*>(wp + kk * 264);
        #pragma unroll
        for (int j = 0; j < 4; ++j) {
            const ulonglong2 a =
                *reinterpret_cast<const ulonglong2*>(ap + kk * 68 + 4 * j);
            asm("fma.rn.f32x2 %0, %1, %2, %0;" : "+l"(acc[2*j  ][0]) : "l"(a.x), "l"(w.x));
            asm("fma.rn.f32x2 %0, %1, %2, %0;" : "+l"(acc[2*j  ][1]) : "l"(a.x), "l"(w.y));
            asm("fma.rn.f32x2 %0, %1, %2, %0;" : "+l"(acc[2*j+1][0]) : "l"(a.y), "l"(w.x));
            asm("fma.rn.f32x2 %0, %1, %2, %0;" : "+l"(acc[2*j+1][1]) : "l"(a.y), "l"(w.y));
        }
    }

    // ---- epilogue: rows 8ty..8ty+7, cols j0+4tx..j0+4tx+3 ----
    #pragma unroll
    for (int r = 0; r < 8; ++r) {
        float f0, f1, f2, f3;
        asm("mov.b64 {%0, %1}, %2;" : "=f"(f0), "=f"(f1) : "l"(acc[r][0]));
        asm("mov.b64 {%0, %1}, %2;" : "=f"(f2), "=f"(f3) : "l"(acc[r][1]));
        float* dst = P + (size_t)(split * BATCH + 8 * ty + r) * N + j0 + 4 * tx;
        *reinterpret_cast<float4*>(dst) = make_float4(f0, f1, f2, f3);
    }
}

// =====================================================================
// Gaussian pseudo-attention + FFN-weight L2 prefetch.
// blocks [0, PF_BLOCKS): stream ffn_w1 / ffn_w2 into L2.
// blocks >= PF_BLOCKS: one warp per (b,i), stream K/V with __ldcs
// (evict-first, so the prefetched weights survive in L2).
// Folds mu/sigma split-K combine; accumulates LN(x) stats via atomics.
// =====================================================================
__global__ __launch_bounds__(256)
void gauss_kernel(const float* __restrict__ Kp,
                  const float* __restrict__ Vp,
                  const float* __restrict__ Qp,
                  const float* __restrict__ mu_b,
                  const float* __restrict__ sig_b,
                  const float* __restrict__ w1,
                  const float* __restrict__ w2)
{
    if (blockIdx.x < PF_BLOCKS) {
        const int pb = blockIdx.x;
        if (pb < PF_BLOCKS / 2)
            prefetch_l2(w1, MFF * NTOK / 4, pb, PF_BLOCKS / 2);
        else
            prefetch_l2(w2, NTOK * MFF / 4, pb - PF_BLOCKS / 2, PF_BLOCKS / 2);
        return;
    }

    const int tid  = threadIdx.x;
    const int w    = (blockIdx.x - PF_BLOCKS) * 8 + (tid >> 5);
    const int lane = tid & 31;
    const int b = w >> 10;
    const int i = w & 1023;

    float mu = mu_b[i];
    float sg = sig_b[i];
    #pragma unroll
    for (int s = 0; s < MS_SPLIT; ++s) {
        mu += g_part[MU_OFF  + (s * BATCH + b) * NTOK + i];
        sg += g_part[SIG_OFF + (s * BATCH + b) * NTOK + i];
    }
    mu = tanhf(mu);
    const float coef = -0.5f / (sg * sg + 1e-8f);

    const float4* K4 = reinterpret_cast<const float4*>(Kp) + (size_t)w * (DDIM / 4);
    const float4* V4 = reinterpret_cast<const float4*>(Vp) + (size_t)w * (DDIM / 4);

    float4 kr[8], vr[8];
    #pragma unroll
    for (int it = 0; it < 8; ++it) kr[it] = __ldcs(&K4[it * 32 + lane]);
    #pragma unroll
    for (int it = 0; it < 8; ++it) vr[it] = __ldcs(&V4[it * 32 + lane]);

    float acc = 0.f;
    #pragma unroll
    for (int it = 0; it < 8; ++it) {
        float d;
        d = kr[it].x - mu; acc += __expf(coef * d * d) * vr[it].x;
        d = kr[it].y - mu; acc += __expf(coef * d * d) * vr[it].y;
        d = kr[it].z - mu; acc += __expf(coef * d * d) * vr[it].z;
        d = kr[it].w - mu; acc += __expf(coef * d * d) * vr[it].w;
    }
    #pragma unroll
    for (int o = 16; o; o >>= 1) acc += __shfl_xor_sync(0xffffffffu, acc, o);

    __shared__ float shv[8];
    if (lane == 0) {
        const float v = acc + Qp[w];
        g_x[w] = v;
        shv[tid >> 5] = v;
    }
    __syncthreads();
    if (tid < 32) {
        float v = (lane < 8) ? shv[lane] : 0.f;
        float s = v, ss = v * v;
        #pragma unroll
        for (int o = 4; o; o >>= 1) {
            s  += __shfl_xor_sync(0xffffffffu, s,  o);
            ss += __shfl_xor_sync(0xffffffffu, ss, o);
        }
        if (lane == 0) {
            atomicAdd(&g_xraw[2 * b],     s);
            atomicAdd(&g_xraw[2 * b + 1], ss);
        }
    }
}

// =====================================================================
// final combine: out = x + b2 + sum of F2_SPLIT partials   (32 x 1024)
// =====================================================================
__global__ void final_kernel(const float* __restrict__ b2,
                             float* __restrict__ out)
{
    const int t  = blockIdx.x * blockDim.x + threadIdx.x;   // 0..8191 float4s
    const int m  = t >> 8;
    const int j4 = t & 255;
    float4 s = reinterpret_cast<const float4*>(g_x)[t];
    const float4 bb = reinterpret_cast<const float4*>(b2)[j4];
    s.x += bb.x; s.y += bb.y; s.z += bb.z; s.w += bb.w;
    #pragma unroll
    for (int sp = 0; sp < F2_SPLIT; ++sp) {
        const float4 p = *reinterpret_cast<const float4*>(
            g_part + W2_OFF + (size_t)(sp * BATCH + m) * NTOK + j4 * 4);
        s.x += p.x; s.y += p.y; s.z += p.z; s.w += p.w;
    }
    reinterpret_cast<float4*>(out)[t] = s;
}

// =====================================================================
extern "C" void kernel_launch(void* const* d_in, const int* in_sizes, int n_in,
                              void* d_out, int out_size)
{
    const float* Q       = (const float*)d_in[0];
    const float* Kt      = (const float*)d_in[1];
    const float* Vt      = (const float*)d_in[2];
    const float* mu_w    = (const float*)d_in[3];
    const float* mu_b    = (const float*)d_in[4];
    const float* sigma_w = (const float*)d_in[5];
    const float* sigma_b = (const float*)d_in[6];
    const float* ffn_w1  = (const float*)d_in[7];
    const float* ffn_b1  = (const float*)d_in[8];
    const float* ffn_w2  = (const float*)d_in[9];
    const float* ffn_b2  = (const float*)d_in[10];
    const float* ln_ff_g = (const float*)d_in[11];
    const float* ln_ff_b = (const float*)d_in[12];
    const float* ln_q_g  = (const float*)d_in[13];
    const float* ln_q_b  = (const float*)d_in[14];
    float* out = (float*)d_out;

    cudaFuncSetAttribute(gemm_kernel<0>,
                         cudaFuncAttributeMaxDynamicSharedMemorySize, GEMM_SMEM);
    cudaFuncSetAttribute(gemm_kernel<1>,
                         cudaFuncAttributeMaxDynamicSharedMemorySize, GEMM_SMEM);
    cudaFuncSetAttribute(gemm_kernel<2>,
                         cudaFuncAttributeMaxDynamicSharedMemorySize, GEMM_SMEM);

    // 1. Q row stats + mu/sigma weight L2 prefetch
    stats_kernel<<<1 + 2 * PF_BLOCKS, 1024>>>(Q, mu_w, sigma_w);

    // 2. mu & sigma partial GEMMs on LN(Q), split-K 16, z selects matrix
    gemm_kernel<0><<<dim3(NTOK / 256, MS_SPLIT, 2), 256, GEMM_SMEM>>>(
        mu_w, sigma_w, NTOK, NTOK, MU_OFF, SIG_OFF - MU_OFF,
        Q, ln_q_g, ln_q_b, nullptr);

    // 3. Gaussian stream + mu/sigma combine + x-stat atomics + FFN W prefetch
    gauss_kernel<<<PF_BLOCKS + (BATCH * NTOK) / 8, 256>>>(
        Kt, Vt, Q, mu_b, sigma_b, ffn_w1, ffn_w2);

    // 4. FFN GEMM 1 on LN(g_x), split-K 16 -> 256 blocks
    gemm_kernel<1><<<dim3(MFF / 256, F1_SPLIT, 1), 256, GEMM_SMEM>>>(
        ffn_w1, ffn_w1, NTOK, MFF, W1_OFF, 0,
        nullptr, ln_ff_g, ln_ff_b, nullptr);

    // 5. FFN GEMM 2 on silu(partials + b1), split-K 64 -> 256 blocks
    gemm_kernel<2><<<dim3(NTOK / 256, F2_SPLIT, 1), 256, GEMM_SMEM>>>(
        ffn_w2, ffn_w2, MFF, NTOK, W2_OFF, 0,
        nullptr, nullptr, nullptr, ffn_b1);

    // 6. out = x + b2 + sum of FFN2 partials
    final_kernel<<<64, 128>>>(ffn_b2, out);
}

// round 8
// speedup vs baseline: 1.1387x; 1.1387x over previous
#include <cuda_runtime.h>
#include <cstdint>

// ---------------- problem constants ----------------
#define BATCH   32
#define NTOK    1024
#define DDIM    1024
#define MFF     4096
#define LN_EPS  1e-5f

#define MS_SPLIT 16
#define F1_SPLIT 16
#define F2_SPLIT 64

// ---------------- scratch ----------------
__device__ float g_x    [BATCH * NTOK];
__device__ float g_qstat[64];                 // (mean, rstd) per Q row
__device__ float g_xraw [64];                 // (sum, sumsq) per x row (atomics)
__device__ float g_part [4194304];            // split-K partials (16 MB)

#define MU_OFF  0                             // 16*32*1024 = 524288
#define SIG_OFF 524288
#define W1_OFF  0                             // 16*32*4096 = 2097152 (reuses mu/sig)
#define W2_OFF  2097152                       // 64*32*1024 = 2097152

// dynamic smem: A panel [64][68] + W panel [64][264]
#define GEMM_SMEM ((64 * 68 + 64 * 264) * 4)  // 84992 B

// =====================================================================
// Q row stats (mean, rstd) + zero the x-stat accumulators. 1 block.
// =====================================================================
__global__ void stats_kernel(const float* __restrict__ Q)
{
    const int tid = threadIdx.x;
    if (tid < 64) g_xraw[tid] = 0.f;
    const int r = tid >> 5, lane = tid & 31;
    const float4* p = reinterpret_cast<const float4*>(Q + r * NTOK);
    float s = 0.f, ss = 0.f;
    #pragma unroll
    for (int i = 0; i < 8; ++i) {
        float4 v = p[lane + 32 * i];
        s  += v.x + v.y + v.z + v.w;
        ss += v.x*v.x + v.y*v.y + v.z*v.z + v.w*v.w;
    }
    #pragma unroll
    for (int o = 16; o; o >>= 1) {
        s  += __shfl_xor_sync(0xffffffffu, s,  o);
        ss += __shfl_xor_sync(0xffffffffu, ss, o);
    }
    if (lane == 0) {
        const float mean = s * (1.0f / NTOK);
        const float var  = ss * (1.0f / NTOK) - mean * mean;
        g_qstat[2 * r]     = mean;
        g_qstat[2 * r + 1] = rsqrtf(var + LN_EPS);
    }
}

// =====================================================================
// Split-K GEMM. Block tile 32(M) x 256(N); K strip 64 per block.
// W loads COALESCED: warp covers 2 n-rows x 16 k-quads -> each LDG.128
// touches 4 lines (vs 32 before). Transposed smem store uses XOR swizzle
// col = n ^ (((kk>>2)&7)<<2) -> conflict-free stores, conflict-free
// LDS.128 reads. Main loop: 64 kk, no syncs, 1 LDS.128 (W) + 4 broadcast
// LDS.128 (dup A) + 16 fma.f32x2 per kk.
// AMODE 0: A = LN(Q) (g_qstat)  1: A = LN(g_x) (g_xraw)
// AMODE 2: A = silu(sum of F1_SPLIT partials + b1)
// gridDim = (N/256, nsplit, nz); z selects W0/W1 (mu/sigma fusion).
// =====================================================================
template<int AMODE>
__global__ __launch_bounds__(256, 2)
void gemm_kernel(const float* __restrict__ W0, const float* __restrict__ W1,
                 int ldw, int N, int partOff, int partStrideZ,
                 const float* __restrict__ Ain,
                 const float* __restrict__ lng, const float* __restrict__ lnb,
                 const float* __restrict__ b1)
{
    extern __shared__ __align__(16) float smem[];
    float* a_s = smem;                  // [64][68] dup A
    float* w_s = smem + 64 * 68;        // [64][264] W, XOR-swizzled columns

    const int tid = threadIdx.x;
    const float* __restrict__ W = (blockIdx.z == 0) ? W0 : W1;
    float* __restrict__ P = g_part + partOff + (size_t)blockIdx.z * partStrideZ;

    const int j0    = blockIdx.x * 256;
    const int split = blockIdx.y;
    const int kOff  = split * 64;

    // ---- coalesced W strip load: 16 LDG.128, nL=4 each, MLP=16 ----
    float4 wv[16];
    #pragma unroll
    for (int j = 0; j < 16; ++j) {
        const int idx = j * 256 + tid;
        const int n   = idx >> 4;            // 0..255
        const int kq  = idx & 15;            // k-quad 0..15
        wv[j] = *reinterpret_cast<const float4*>(
            W + (size_t)(j0 + n) * ldw + kOff + kq * 4);
    }

    // ---- build A panel (whole 64-k strip) ----
    const int ra = tid >> 2, kg = (tid & 3) * 16;   // threads 0..127 active
    float mean = 0.f, rs = 0.f;
    if (AMODE == 0) { mean = g_qstat[2 * ra]; rs = g_qstat[2 * ra + 1]; }
    if (AMODE == 1) {
        const float s  = g_xraw[2 * ra];
        const float ss = g_xraw[2 * ra + 1];
        mean = s * (1.0f / NTOK);
        rs   = rsqrtf(ss * (1.0f / NTOK) - mean * mean + LN_EPS);
    }
    const float* Arow = (AMODE == 1) ? (g_x + ra * NTOK)
                      : (AMODE == 0) ? (Ain + ra * NTOK) : nullptr;

    if (tid < 128) {
        #pragma unroll
        for (int h = 0; h < 4; ++h) {
            const int klocal = kg + h * 4;
            const int kc     = kOff + klocal;
            float av[4];
            if (AMODE < 2) {
                const float4 fa = *reinterpret_cast<const float4*>(Arow + kc);
                const float4 fg = *reinterpret_cast<const float4*>(lng + kc);
                const float4 fb = *reinterpret_cast<const float4*>(lnb + kc);
                av[0] = (fa.x - mean) * rs * fg.x + fb.x;
                av[1] = (fa.y - mean) * rs * fg.y + fb.y;
                av[2] = (fa.z - mean) * rs * fg.z + fb.z;
                av[3] = (fa.w - mean) * rs * fg.w + fb.w;
            } else {
                float4 v = *reinterpret_cast<const float4*>(b1 + kc);
                #pragma unroll
                for (int s = 0; s < F1_SPLIT; ++s) {
                    const float4 p = *reinterpret_cast<const float4*>(
                        g_part + W1_OFF + (size_t)(s * BATCH + ra) * MFF + kc);
                    v.x += p.x; v.y += p.y; v.z += p.z; v.w += p.w;
                }
                av[0] = v.x / (1.0f + __expf(-v.x));
                av[1] = v.y / (1.0f + __expf(-v.y));
                av[2] = v.z / (1.0f + __expf(-v.z));
                av[3] = v.w / (1.0f + __expf(-v.w));
            }
            #pragma unroll
            for (int j = 0; j < 4; ++j)
                *reinterpret_cast<float2*>(&a_s[(klocal + j) * 68 + 2 * ra]) =
                    make_float2(av[j], av[j]);
        }
    }

    // ---- transposed + swizzled W store (conflict-free) ----
    #pragma unroll
    for (int j = 0; j < 16; ++j) {
        const int idx = j * 256 + tid;
        const int n   = idx >> 4;
        const int kq  = idx & 15;
        const int col = n ^ ((kq & 7) << 2);
        w_s[(kq * 4 + 0) * 264 + col] = wv[j].x;
        w_s[(kq * 4 + 1) * 264 + col] = wv[j].y;
        w_s[(kq * 4 + 2) * 264 + col] = wv[j].z;
        w_s[(kq * 4 + 3) * 264 + col] = wv[j].w;
    }
    __syncthreads();

    // ---- main loop: 64 kk, no syncs ----
    const int tx = tid & 63, ty = tid >> 6;
    const float* ap = a_s + 16 * ty;

    unsigned long long acc[8][2];
    #pragma unroll
    for (int r = 0; r < 8; ++r) { acc[r][0] = 0ull; acc[r][1] = 0ull; }

    #pragma unroll
    for (int kq2 = 0; kq2 < 16; ++kq2) {
        const float* wcol = w_s + ((4 * tx) ^ ((kq2 & 7) << 2));
        #pragma unroll
        for (int j2 = 0; j2 < 4; ++j2) {
            const int kk = kq2 * 4 + j2;
            const ulonglong2 w =
                *reinterpret_cast<const ulonglong2*>(wcol + kk * 264);
            #pragma unroll
            for (int j = 0; j < 4; ++j) {
                const ulonglong2 a =
                    *reinterpret_cast<const ulonglong2*>(ap + kk * 68 + 4 * j);
                asm("fma.rn.f32x2 %0, %1, %2, %0;" : "+l"(acc[2*j  ][0]) : "l"(a.x), "l"(w.x));
                asm("fma.rn.f32x2 %0, %1, %2, %0;" : "+l"(acc[2*j  ][1]) : "l"(a.x), "l"(w.y));
                asm("fma.rn.f32x2 %0, %1, %2, %0;" : "+l"(acc[2*j+1][0]) : "l"(a.y), "l"(w.x));
                asm("fma.rn.f32x2 %0, %1, %2, %0;" : "+l"(acc[2*j+1][1]) : "l"(a.y), "l"(w.y));
            }
        }
    }

    // ---- epilogue: rows 8ty..8ty+7, cols j0+4tx..j0+4tx+3 ----
    #pragma unroll
    for (int r = 0; r < 8; ++r) {
        float f0, f1, f2, f3;
        asm("mov.b64 {%0, %1}, %2;" : "=f"(f0), "=f"(f1) : "l"(acc[r][0]));
        asm("mov.b64 {%0, %1}, %2;" : "=f"(f2), "=f"(f3) : "l"(acc[r][1]));
        float* dst = P + (size_t)(split * BATCH + 8 * ty + r) * N + j0 + 4 * tx;
        *reinterpret_cast<float4*>(dst) = make_float4(f0, f1, f2, f3);
    }
}

// =====================================================================
// Gaussian pseudo-attention: one warp per (b,i), streams K/V (256 MB)
// with all 16 row loads batched up front (MLP=16). Folds mu/sigma
// split-K combine; accumulates LN(x) stats via atomics.
// =====================================================================
__global__ __launch_bounds__(256)
void gauss_kernel(const float* __restrict__ Kp,
                  const float* __restrict__ Vp,
                  const float* __restrict__ Qp,
                  const float* __restrict__ mu_b,
                  const float* __restrict__ sig_b)
{
    const int tid  = threadIdx.x;
    const int w    = blockIdx.x * 8 + (tid >> 5);
    const int lane = tid & 31;
    const int b = w >> 10;
    const int i = w & 1023;

    float mu = mu_b[i];
    float sg = sig_b[i];
    #pragma unroll
    for (int s = 0; s < MS_SPLIT; ++s) {
        mu += g_part[MU_OFF  + (s * BATCH + b) * NTOK + i];
        sg += g_part[SIG_OFF + (s * BATCH + b) * NTOK + i];
    }
    mu = tanhf(mu);
    const float coef = -0.5f / (sg * sg + 1e-8f);

    const float4* K4 = reinterpret_cast<const float4*>(Kp) + (size_t)w * (DDIM / 4);
    const float4* V4 = reinterpret_cast<const float4*>(Vp) + (size_t)w * (DDIM / 4);

    float4 kr[8], vr[8];
    #pragma unroll
    for (int it = 0; it < 8; ++it) kr[it] = __ldcs(&K4[it * 32 + lane]);
    #pragma unroll
    for (int it = 0; it < 8; ++it) vr[it] = __ldcs(&V4[it * 32 + lane]);

    float acc = 0.f;
    #pragma unroll
    for (int it = 0; it < 8; ++it) {
        float d;
        d = kr[it].x - mu; acc += __expf(coef * d * d) * vr[it].x;
        d = kr[it].y - mu; acc += __expf(coef * d * d) * vr[it].y;
        d = kr[it].z - mu; acc += __expf(coef * d * d) * vr[it].z;
        d = kr[it].w - mu; acc += __expf(coef * d * d) * vr[it].w;
    }
    #pragma unroll
    for (int o = 16; o; o >>= 1) acc += __shfl_xor_sync(0xffffffffu, acc, o);

    __shared__ float shv[8];
    if (lane == 0) {
        const float v = acc + Qp[w];
        g_x[w] = v;
        shv[tid >> 5] = v;
    }
    __syncthreads();
    if (tid < 32) {
        float v = (lane < 8) ? shv[lane] : 0.f;
        float s = v, ss = v * v;
        #pragma unroll
        for (int o = 4; o; o >>= 1) {
            s  += __shfl_xor_sync(0xffffffffu, s,  o);
            ss += __shfl_xor_sync(0xffffffffu, ss, o);
        }
        if (lane == 0) {
            atomicAdd(&g_xraw[2 * b],     s);
            atomicAdd(&g_xraw[2 * b + 1], ss);
        }
    }
}

// =====================================================================
// final combine: out = x + b2 + sum of F2_SPLIT partials   (32 x 1024)
// =====================================================================
__global__ void final_kernel(const float* __restrict__ b2,
                             float* __restrict__ out)
{
    const int t  = blockIdx.x * blockDim.x + threadIdx.x;   // 0..8191 float4s
    const int m  = t >> 8;
    const int j4 = t & 255;
    float4 s = reinterpret_cast<const float4*>(g_x)[t];
    const float4 bb = reinterpret_cast<const float4*>(b2)[j4];
    s.x += bb.x; s.y += bb.y; s.z += bb.z; s.w += bb.w;
    #pragma unroll
    for (int sp = 0; sp < F2_SPLIT; ++sp) {
        const float4 p = *reinterpret_cast<const float4*>(
            g_part + W2_OFF + (size_t)(sp * BATCH + m) * NTOK + j4 * 4);
        s.x += p.x; s.y += p.y; s.z += p.z; s.w += p.w;
    }
    reinterpret_cast<float4*>(out)[t] = s;
}

// =====================================================================
extern "C" void kernel_launch(void* const* d_in, const int* in_sizes, int n_in,
                              void* d_out, int out_size)
{
    const float* Q       = (const float*)d_in[0];
    const float* Kt      = (const float*)d_in[1];
    const float* Vt      = (const float*)d_in[2];
    const float* mu_w    = (const float*)d_in[3];
    const float* mu_b    = (const float*)d_in[4];
    const float* sigma_w = (const float*)d_in[5];
    const float* sigma_b = (const float*)d_in[6];
    const float* ffn_w1  = (const float*)d_in[7];
    const float* ffn_b1  = (const float*)d_in[8];
    const float* ffn_w2  = (const float*)d_in[9];
    const float* ffn_b2  = (const float*)d_in[10];
    const float* ln_ff_g = (const float*)d_in[11];
    const float* ln_ff_b = (const float*)d_in[12];
    const float* ln_q_g  = (const float*)d_in[13];
    const float* ln_q_b  = (const float*)d_in[14];
    float* out = (float*)d_out;

    cudaFuncSetAttribute(gemm_kernel<0>,
                         cudaFuncAttributeMaxDynamicSharedMemorySize, GEMM_SMEM);
    cudaFuncSetAttribute(gemm_kernel<1>,
                         cudaFuncAttributeMaxDynamicSharedMemorySize, GEMM_SMEM);
    cudaFuncSetAttribute(gemm_kernel<2>,
                         cudaFuncAttributeMaxDynamicSharedMemorySize, GEMM_SMEM);

    // 1. Q row stats + zero x-stat accumulators
    stats_kernel<<<1, 1024>>>(Q);

    // 2. mu & sigma partial GEMMs on LN(Q), split-K 16, z selects matrix
    gemm_kernel<0><<<dim3(NTOK / 256, MS_SPLIT, 2), 256, GEMM_SMEM>>>(
        mu_w, sigma_w, NTOK, NTOK, MU_OFF, SIG_OFF - MU_OFF,
        Q, ln_q_g, ln_q_b, nullptr);

    // 3. Gaussian stream + mu/sigma combine + x-stat atomics
    gauss_kernel<<<(BATCH * NTOK) / 8, 256>>>(Kt, Vt, Q, mu_b, sigma_b);

    // 4. FFN GEMM 1 on LN(g_x), split-K 16 -> 256 blocks
    gemm_kernel<1><<<dim3(MFF / 256, F1_SPLIT, 1), 256, GEMM_SMEM>>>(
        ffn_w1, ffn_w1, NTOK, MFF, W1_OFF, 0,
        nullptr, ln_ff_g, ln_ff_b, nullptr);

    // 5. FFN GEMM 2 on silu(partials + b1), split-K 64 -> 256 blocks
    gemm_kernel<2><<<dim3(NTOK / 256, F2_SPLIT, 1), 256, GEMM_SMEM>>>(
        ffn_w2, ffn_w2, MFF, NTOK, W2_OFF, 0,
        nullptr, nullptr, nullptr, ffn_b1);

    // 6. out = x + b2 + sum of FFN2 partials
    final_kernel<<<64, 128>>>(ffn_b2, out);
}